// round 1
// baseline (speedup 1.0000x reference)
#include <cuda_runtime.h>
#include <math.h>

#define BATCH 1024
#define FRAMES 31
#define NFFT 2048
#define HID 256

// Scratch (allocation-free rule: __device__ globals)
__device__ float g_h0[BATCH * NFFT];   // real part of mean-spectrum
__device__ float g_h1[BATCH * HID];
__device__ float g_h2[BATCH * HID];

// ---------------------------------------------------------------------------
// Kernel 1: fused frame-mean + 2048-pt radix-2 FFT (real part out).
// One block per batch row. Reads 31*2048 floats, FFT in shared memory.
// ---------------------------------------------------------------------------
__global__ __launch_bounds__(512) void fftmean_kernel(const float* __restrict__ x) {
    __shared__ float2 s[NFFT];         // 16 KB
    __shared__ float2 tw[NFFT / 2];    // 8 KB twiddle table

    const int b = blockIdx.x;
    const float* __restrict__ xin = x + (size_t)b * (FRAMES * NFFT);

    // frame mean, stored bit-reversed into smem (imag = 0)
    for (int i = threadIdx.x; i < NFFT; i += blockDim.x) {
        float acc = 0.f;
        #pragma unroll
        for (int t = 0; t < FRAMES; t++) acc += xin[t * NFFT + i];
        unsigned r = __brev((unsigned)i) >> 21;   // 11-bit reversal
        s[r] = make_float2(acc * (1.0f / FRAMES), 0.f);
    }
    // twiddles: tw[j] = exp(-2*pi*i*j/2048)
    for (int j = threadIdx.x; j < NFFT / 2; j += blockDim.x) {
        float sv, cv;
        sincosf(-6.28318530717958647692f * (float)j * (1.0f / NFFT), &sv, &cv);
        tw[j] = make_float2(cv, sv);
    }
    __syncthreads();

    // 11 radix-2 DIT stages
    #pragma unroll 1
    for (int st = 1; st <= 11; st++) {
        const int half = 1 << (st - 1);
        for (int t = threadIdx.x; t < NFFT / 2; t += blockDim.x) {
            const int j   = t & (half - 1);
            const int pos = ((t >> (st - 1)) << st) + j;
            const float2 w = tw[j << (11 - st)];
            const float2 u = s[pos];
            const float2 v = s[pos + half];
            const float vr = v.x * w.x - v.y * w.y;
            const float vi = v.x * w.y + v.y * w.x;
            s[pos]        = make_float2(u.x + vr, u.y + vi);
            s[pos + half] = make_float2(u.x - vr, u.y - vi);
        }
        __syncthreads();
    }

    float* __restrict__ out = g_h0 + (size_t)b * NFFT;
    for (int i = threadIdx.x; i < NFFT; i += blockDim.x) out[i] = s[i].x;
}

// ---------------------------------------------------------------------------
// Kernel 2/3: tiled SGEMM  C[M,N] = act(A[M,K] * W[N,K]^T + bias[N])
// BM=64, BN=64, BK=16, TM=TN=4, 256 threads.
// ---------------------------------------------------------------------------
template <bool RELU>
__global__ __launch_bounds__(256) void gemm_kernel(
    const float* __restrict__ A, const float* __restrict__ W,
    const float* __restrict__ bias, float* __restrict__ C,
    int M, int N, int K)
{
    const int BM = 64, BN = 64, BK = 16;
    __shared__ float As[BK][BM + 1];
    __shared__ float Bs[BK][BN + 1];

    const int t  = threadIdx.x;        // 0..255
    const int tx = t & 15;             // n-dir
    const int ty = t >> 4;             // m-dir
    const int m0 = blockIdx.x * BM;
    const int n0 = blockIdx.y * BN;

    float acc[4][4] = {};

    for (int k0 = 0; k0 < K; k0 += BK) {
        #pragma unroll
        for (int i = 0; i < 4; i++) {
            int lin = t + i * 256;
            int kk = lin & 15, mm = lin >> 4;
            As[kk][mm] = A[(size_t)(m0 + mm) * K + k0 + kk];
        }
        #pragma unroll
        for (int i = 0; i < 4; i++) {
            int lin = t + i * 256;
            int kk = lin & 15, nn = lin >> 4;
            Bs[kk][nn] = W[(size_t)(n0 + nn) * K + k0 + kk];
        }
        __syncthreads();

        #pragma unroll
        for (int kk = 0; kk < BK; kk++) {
            float a[4], bb[4];
            #pragma unroll
            for (int i = 0; i < 4; i++) a[i]  = As[kk][ty * 4 + i];
            #pragma unroll
            for (int j = 0; j < 4; j++) bb[j] = Bs[kk][tx * 4 + j];
            #pragma unroll
            for (int i = 0; i < 4; i++)
                #pragma unroll
                for (int j = 0; j < 4; j++)
                    acc[i][j] += a[i] * bb[j];
        }
        __syncthreads();
    }

    #pragma unroll
    for (int i = 0; i < 4; i++) {
        const int m = m0 + ty * 4 + i;
        #pragma unroll
        for (int j = 0; j < 4; j++) {
            const int n = n0 + tx * 4 + j;
            float v = acc[i][j] + bias[n];
            if (RELU) v = fmaxf(v, 0.f);
            C[(size_t)m * N + n] = v;
        }
    }
}

// ---------------------------------------------------------------------------
// Kernel 4: out[b] = sigmoid(dot(h2[b,:], W3) + b3). One warp per row.
// ---------------------------------------------------------------------------
__global__ __launch_bounds__(256) void out_kernel(
    const float* __restrict__ W3, const float* __restrict__ b3,
    float* __restrict__ out)
{
    const int warp = (blockIdx.x * blockDim.x + threadIdx.x) >> 5;
    const int lane = threadIdx.x & 31;
    if (warp >= BATCH) return;
    const float* __restrict__ h = g_h2 + (size_t)warp * HID;
    float acc = 0.f;
    #pragma unroll
    for (int i = lane; i < HID; i += 32) acc += h[i] * W3[i];
    #pragma unroll
    for (int off = 16; off; off >>= 1)
        acc += __shfl_down_sync(0xffffffffu, acc, off);
    if (lane == 0) out[warp] = 1.f / (1.f + expf(-(acc + b3[0])));
}

// ---------------------------------------------------------------------------
extern "C" void kernel_launch(void* const* d_in, const int* in_sizes, int n_in,
                              void* d_out, int out_size)
{
    const float* x  = (const float*)d_in[0];
    const float* W1 = (const float*)d_in[1];
    const float* b1 = (const float*)d_in[2];
    const float* W2 = (const float*)d_in[3];
    const float* b2 = (const float*)d_in[4];
    const float* W3 = (const float*)d_in[5];
    const float* b3 = (const float*)d_in[6];
    float* out = (float*)d_out;

    float *p_h0, *p_h1, *p_h2;
    cudaGetSymbolAddress((void**)&p_h0, g_h0);
    cudaGetSymbolAddress((void**)&p_h1, g_h1);
    cudaGetSymbolAddress((void**)&p_h2, g_h2);

    fftmean_kernel<<<BATCH, 512>>>(x);

    dim3 g1(BATCH / 64, HID / 64);
    gemm_kernel<true><<<g1, 256>>>(p_h0, W1, b1, p_h1, BATCH, HID, NFFT);
    gemm_kernel<true><<<g1, 256>>>(p_h1, W2, b2, p_h2, BATCH, HID, HID);

    out_kernel<<<BATCH * 32 / 256, 256>>>(W3, b3, out);
}

// round 2
// speedup vs baseline: 1.3884x; 1.3884x over previous
#include <cuda_runtime.h>
#include <math.h>

#define BATCH 1024
#define FRAMES 31
#define NFFT 2048
#define N2 1024           // packed complex FFT length
#define KF 1040           // folded K (1025 padded to 16-multiple)
#define HID 256

// Scratch (allocation-free rule: __device__ globals)
__device__ __align__(16) float g_h0[BATCH * KF];    // Re-spectrum, folded K layout
__device__ __align__(16) float g_w1f[HID * KF];     // folded W1
__device__ __align__(16) float g_h1[BATCH * HID];
__device__ __align__(16) float g_h2[BATCH * HID];

// ---------------------------------------------------------------------------
// Fold W1: W1f[n,k] = W1[n,k] + W1[n,2048-k] for 1<=k<=1023; ends unfolded;
// pad cols 1025..1039 with zeros.
// ---------------------------------------------------------------------------
__global__ __launch_bounds__(256) void fold_w1_kernel(const float* __restrict__ W1) {
    int idx = blockIdx.x * blockDim.x + threadIdx.x;
    if (idx >= HID * KF) return;
    int n = idx / KF;
    int k = idx - n * KF;
    float v;
    if (k == 0)             v = W1[(size_t)n * NFFT];
    else if (k < 1024)      v = W1[(size_t)n * NFFT + k] + W1[(size_t)n * NFFT + (NFFT - k)];
    else if (k == 1024)     v = W1[(size_t)n * NFFT + 1024];
    else                    v = 0.f;
    g_w1f[idx] = v;
}

// ---------------------------------------------------------------------------
// Kernel 1: fused frame-mean + real-packed 1024-pt FFT + untangle.
// One block (512 thr) per batch row. z[j] = m[2j] + i*m[2j+1].
// Outputs Re X[k], k in [0,1024], padded to KF with zeros.
// ---------------------------------------------------------------------------
__global__ __launch_bounds__(512) void fftmean_kernel(const float* __restrict__ x) {
    __shared__ float2 s[N2];        // 8 KB
    __shared__ float2 tw[N2 / 2];   // 4 KB

    const int b   = blockIdx.x;
    const int tid = threadIdx.x;
    const float2* __restrict__ xin =
        (const float2*)(x + (size_t)b * (FRAMES * NFFT));

    // frame mean (float2-vectorized), stored bit-reversed (10-bit)
    for (int j = tid; j < N2; j += 512) {
        float ar = 0.f, ai = 0.f;
        #pragma unroll
        for (int t = 0; t < FRAMES; t++) {
            float2 v = xin[t * N2 + j];
            ar += v.x; ai += v.y;
        }
        unsigned r = __brev((unsigned)j) >> 22;
        s[r] = make_float2(ar * (1.0f / FRAMES), ai * (1.0f / FRAMES));
    }
    if (tid < N2 / 2) {
        float sv, cv;
        sincosf(-6.28318530717958647692f * (float)tid * (1.0f / N2), &sv, &cv);
        tw[tid] = make_float2(cv, sv);
    }
    __syncthreads();

    // 10 radix-2 DIT stages, exactly one butterfly per thread per stage
    #pragma unroll 1
    for (int st = 1; st <= 10; st++) {
        const int half = 1 << (st - 1);
        const int j    = tid & (half - 1);
        const int pos  = ((tid >> (st - 1)) << st) + j;
        const float2 w = tw[j << (10 - st)];
        const float2 u = s[pos];
        const float2 v = s[pos + half];
        const float vr = v.x * w.x - v.y * w.y;
        const float vi = v.x * w.y + v.y * w.x;
        s[pos]        = make_float2(u.x + vr, u.y + vi);
        s[pos + half] = make_float2(u.x - vr, u.y - vi);
        __syncthreads();
    }

    // untangle: Re X[k] and Re X[1024-k] from Z[k], Z[(1024-k)&1023]
    float* __restrict__ out = g_h0 + (size_t)b * KF;
    #pragma unroll 1
    for (int k = tid; k <= N2 / 2; k += 512) {   // k = tid, and k=512 for tid 0
        const float2 zk = s[k];
        const float2 z2 = s[(N2 - k) & (N2 - 1)];
        float sn, cs;
        sincosf(3.14159265358979323846f * (float)k * (1.0f / N2), &sn, &cs);
        const float sumr = zk.x + z2.x;
        const float sumi = zk.y + z2.y;
        const float difr = zk.x - z2.x;
        out[k]      = 0.5f * (sumr + cs * sumi - sn * difr);
        out[N2 - k] = 0.5f * (sumr - cs * sumi + sn * difr);
    }
    if (tid < KF - N2 - 1) out[N2 + 1 + tid] = 0.f;   // zero pad 1025..1039
}

// ---------------------------------------------------------------------------
// Tiled SGEMM  C[M,N] = act(A[M,K] * W[N,K]^T + bias[N])
// BM=64, BN=32, BK=16, 256 threads, thread tile 4x2, float4 smem fills.
// ---------------------------------------------------------------------------
template <bool RELU>
__global__ __launch_bounds__(256) void gemm_kernel(
    const float* __restrict__ A, const float* __restrict__ W,
    const float* __restrict__ bias, float* __restrict__ C,
    int N, int K)
{
    const int BM = 64, BN = 32, BK = 16;
    __shared__ float As[BK][BM + 1];
    __shared__ float Bs[BK][BN + 1];

    const int t  = threadIdx.x;          // 0..255
    const int tx = t & 15;               // n-dir (x2)
    const int ty = t >> 4;               // m-dir (x4)
    const int m0 = blockIdx.x * BM;
    const int n0 = blockIdx.y * BN;

    const int a_mm = t >> 2;             // 0..63
    const int a_kk = (t & 3) * 4;        // 0,4,8,12
    const int b_nn = (t & 127) >> 2;     // 0..31
    const int b_kk = ((t & 3) + ((t >> 7) << 2)) * 4; // hmm — see below

    float acc[4][2] = {};

    for (int k0 = 0; k0 < K; k0 += BK) {
        // As: 64x16 floats = 256 float4, one per thread
        {
            float4 va = *(const float4*)&A[(size_t)(m0 + a_mm) * K + k0 + a_kk];
            As[a_kk + 0][a_mm] = va.x;
            As[a_kk + 1][a_mm] = va.y;
            As[a_kk + 2][a_mm] = va.z;
            As[a_kk + 3][a_mm] = va.w;
        }
        // Bs: 32x16 floats = 128 float4, threads 0..127
        if (t < 128) {
            int nn = t >> 2;
            int kk = (t & 3) * 4;
            float4 vb = *(const float4*)&W[(size_t)(n0 + nn) * K + k0 + kk];
            Bs[kk + 0][nn] = vb.x;
            Bs[kk + 1][nn] = vb.y;
            Bs[kk + 2][nn] = vb.z;
            Bs[kk + 3][nn] = vb.w;
        }
        __syncthreads();

        #pragma unroll
        for (int kk = 0; kk < BK; kk++) {
            float a[4], bb[2];
            #pragma unroll
            for (int i = 0; i < 4; i++) a[i]  = As[kk][ty * 4 + i];
            #pragma unroll
            for (int j = 0; j < 2; j++) bb[j] = Bs[kk][tx * 2 + j];
            #pragma unroll
            for (int i = 0; i < 4; i++)
                #pragma unroll
                for (int j = 0; j < 2; j++)
                    acc[i][j] += a[i] * bb[j];
        }
        __syncthreads();
    }

    #pragma unroll
    for (int i = 0; i < 4; i++) {
        const int m = m0 + ty * 4 + i;
        #pragma unroll
        for (int j = 0; j < 2; j++) {
            const int n = n0 + tx * 2 + j;
            float v = acc[i][j] + bias[n];
            if (RELU) v = fmaxf(v, 0.f);
            C[(size_t)m * N + n] = v;
        }
    }
}

// ---------------------------------------------------------------------------
// out[b] = sigmoid(dot(h2[b,:], W3) + b3). One warp per row.
// ---------------------------------------------------------------------------
__global__ __launch_bounds__(256) void out_kernel(
    const float* __restrict__ W3, const float* __restrict__ b3,
    float* __restrict__ out)
{
    const int warp = (blockIdx.x * blockDim.x + threadIdx.x) >> 5;
    const int lane = threadIdx.x & 31;
    if (warp >= BATCH) return;
    const float* __restrict__ h = g_h2 + (size_t)warp * HID;
    float acc = 0.f;
    #pragma unroll
    for (int i = lane; i < HID; i += 32) acc += h[i] * W3[i];
    #pragma unroll
    for (int off = 16; off; off >>= 1)
        acc += __shfl_down_sync(0xffffffffu, acc, off);
    if (lane == 0) out[warp] = 1.f / (1.f + expf(-(acc + b3[0])));
}

// ---------------------------------------------------------------------------
extern "C" void kernel_launch(void* const* d_in, const int* in_sizes, int n_in,
                              void* d_out, int out_size)
{
    const float* x  = (const float*)d_in[0];
    const float* W1 = (const float*)d_in[1];
    const float* b1 = (const float*)d_in[2];
    const float* W2 = (const float*)d_in[3];
    const float* b2 = (const float*)d_in[4];
    const float* W3 = (const float*)d_in[5];
    const float* b3 = (const float*)d_in[6];
    float* out = (float*)d_out;

    float *p_h0, *p_w1f, *p_h1, *p_h2;
    cudaGetSymbolAddress((void**)&p_h0,  g_h0);
    cudaGetSymbolAddress((void**)&p_w1f, g_w1f);
    cudaGetSymbolAddress((void**)&p_h1,  g_h1);
    cudaGetSymbolAddress((void**)&p_h2,  g_h2);

    fold_w1_kernel<<<(HID * KF + 255) / 256, 256>>>(W1);
    fftmean_kernel<<<BATCH, 512>>>(x);

    dim3 g1(BATCH / 64, HID / 32);   // (16, 8) = 128 CTAs
    gemm_kernel<true><<<g1, 256>>>(p_h0, p_w1f, b1, p_h1, HID, KF);
    gemm_kernel<true><<<g1, 256>>>(p_h1, W2,    b2, p_h2, HID, HID);

    out_kernel<<<BATCH * 32 / 256, 256>>>(W3, b3, out);
}

// round 3
// speedup vs baseline: 2.2036x; 1.5872x over previous
#include <cuda_runtime.h>
#include <math.h>

#define BATCH 1024
#define FRAMES 31
#define NFFT 2048
#define N2 1024            // packed complex FFT length
#define KF 1088            // folded K: 1025 padded to 4*272 (272 = 17*16)
#define KSPLIT 4
#define KCH (KF / KSPLIT)  // 272
#define HID 256

// Scratch (allocation-free rule: __device__ globals)
__device__ __align__(16) float g_mean[BATCH * NFFT];       // 8 MB frame-mean
__device__ __align__(16) float g_h0[BATCH * KF];           // folded Re-spectrum
__device__ __align__(16) float g_w1f[HID * KF];            // folded W1
__device__ __align__(16) float g_p1[KSPLIT][BATCH * HID];  // split-K partials
__device__ __align__(16) float g_h1[BATCH * HID];
__device__ __align__(16) float g_h2[BATCH * HID];

// ---------------------------------------------------------------------------
// Fold W1: W1f[n,k] = W1[n,k] + W1[n,2048-k] for 1<=k<=1023; ends unfolded;
// zero-pad cols 1025..KF-1.
// ---------------------------------------------------------------------------
__global__ __launch_bounds__(256) void fold_w1_kernel(const float* __restrict__ W1) {
    int idx = blockIdx.x * blockDim.x + threadIdx.x;
    if (idx >= HID * KF) return;
    int n = idx / KF;
    int k = idx - n * KF;
    float v;
    if (k == 0)             v = W1[(size_t)n * NFFT];
    else if (k < 1024)      v = W1[(size_t)n * NFFT + k] + W1[(size_t)n * NFFT + (NFFT - k)];
    else if (k == 1024)     v = W1[(size_t)n * NFFT + 1024];
    else                    v = 0.f;
    g_w1f[idx] = v;
}

// ---------------------------------------------------------------------------
// Pure-bandwidth frame mean: one float4 output per thread, 31 strided loads.
// grid = BATCH*NFFT/4/256 = 2048 blocks. Minimal registers, max MLP.
// ---------------------------------------------------------------------------
__global__ __launch_bounds__(256) void mean_kernel(const float* __restrict__ x) {
    const int idx = blockIdx.x * 256 + threadIdx.x;          // 0 .. 524287
    const int b   = idx >> 9;                                // / 512 float4 per row
    const int c   = idx & 511;
    const float4* __restrict__ p =
        (const float4*)x + (size_t)b * (FRAMES * NFFT / 4) + c;
    float4 acc = make_float4(0.f, 0.f, 0.f, 0.f);
    #pragma unroll
    for (int t = 0; t < FRAMES; t++) {
        float4 v = p[t * (NFFT / 4)];
        acc.x += v.x; acc.y += v.y; acc.z += v.z; acc.w += v.w;
    }
    const float inv = 1.0f / FRAMES;
    acc.x *= inv; acc.y *= inv; acc.z *= inv; acc.w *= inv;
    ((float4*)g_mean)[idx] = acc;
}

// ---------------------------------------------------------------------------
// Real-packed 1024-pt FFT + untangle. One block (512 thr) per batch row.
// Reads g_mean (L2-resident), outputs Re X[k], k in [0,1024], zero-pad to KF.
// ---------------------------------------------------------------------------
__global__ __launch_bounds__(512) void fft_kernel() {
    __shared__ float2 s[N2];        // 8 KB
    __shared__ float2 tw[N2 / 2];   // 4 KB

    const int b   = blockIdx.x;
    const int tid = threadIdx.x;
    const float2* __restrict__ m = (const float2*)g_mean + (size_t)b * N2;

    // load packed z[j] = mean[2j] + i*mean[2j+1], store bit-reversed (10-bit)
    #pragma unroll
    for (int j = tid; j < N2; j += 512) {
        float2 v = m[j];
        unsigned r = __brev((unsigned)j) >> 22;
        s[r] = v;
    }
    if (tid < N2 / 2) {
        float sv, cv;
        sincosf(-6.28318530717958647692f * (float)tid * (1.0f / N2), &sv, &cv);
        tw[tid] = make_float2(cv, sv);
    }
    __syncthreads();

    // 10 radix-2 DIT stages, one butterfly per thread per stage
    #pragma unroll 1
    for (int st = 1; st <= 10; st++) {
        const int half = 1 << (st - 1);
        const int j    = tid & (half - 1);
        const int pos  = ((tid >> (st - 1)) << st) + j;
        const float2 w = tw[j << (10 - st)];
        const float2 u = s[pos];
        const float2 v = s[pos + half];
        const float vr = v.x * w.x - v.y * w.y;
        const float vi = v.x * w.y + v.y * w.x;
        s[pos]        = make_float2(u.x + vr, u.y + vi);
        s[pos + half] = make_float2(u.x - vr, u.y - vi);
        __syncthreads();
    }

    // untangle: Re X[k] and Re X[1024-k] from Z[k], Z[(1024-k)&1023]
    float* __restrict__ out = g_h0 + (size_t)b * KF;
    #pragma unroll 1
    for (int k = tid; k <= N2 / 2; k += 512) {
        const float2 zk = s[k];
        const float2 z2 = s[(N2 - k) & (N2 - 1)];
        float sn, cs;
        sincosf(3.14159265358979323846f * (float)k * (1.0f / N2), &sn, &cs);
        const float sumr = zk.x + z2.x;
        const float sumi = zk.y + z2.y;
        const float difr = zk.x - z2.x;
        out[k]      = 0.5f * (sumr + cs * sumi - sn * difr);
        out[N2 - k] = 0.5f * (sumr - cs * sumi + sn * difr);
    }
    for (int k = N2 + 1 + tid; k < KF; k += 512) out[k] = 0.f;  // pad 1025..1087
}

// ---------------------------------------------------------------------------
// Split-K SGEMM partial: P[z][M,N] = A[M, z*KCH:(z+1)*KCH] * W[N, ...]^T
// BM=64, BN=32, BK=16, 256 threads, thread tile 4x2, float4 smem fills.
// ---------------------------------------------------------------------------
__global__ __launch_bounds__(256) void gemm_splitk_kernel(
    const float* __restrict__ A, const float* __restrict__ W)
{
    const int BM = 64, BN = 32, BK = 16;
    __shared__ float As[BK][BM + 1];
    __shared__ float Bs[BK][BN + 1];

    const int t  = threadIdx.x;
    const int tx = t & 15;
    const int ty = t >> 4;
    const int m0 = blockIdx.x * BM;
    const int n0 = blockIdx.y * BN;
    const int z  = blockIdx.z;
    const int kbeg = z * KCH;

    const int a_mm = t >> 2;
    const int a_kk = (t & 3) * 4;

    float acc[4][2] = {};

    for (int k0 = kbeg; k0 < kbeg + KCH; k0 += BK) {
        {
            float4 va = *(const float4*)&A[(size_t)(m0 + a_mm) * KF + k0 + a_kk];
            As[a_kk + 0][a_mm] = va.x;
            As[a_kk + 1][a_mm] = va.y;
            As[a_kk + 2][a_mm] = va.z;
            As[a_kk + 3][a_mm] = va.w;
        }
        if (t < 128) {
            int nn = t >> 2;
            int kk = (t & 3) * 4;
            float4 vb = *(const float4*)&W[(size_t)(n0 + nn) * KF + k0 + kk];
            Bs[kk + 0][nn] = vb.x;
            Bs[kk + 1][nn] = vb.y;
            Bs[kk + 2][nn] = vb.z;
            Bs[kk + 3][nn] = vb.w;
        }
        __syncthreads();

        #pragma unroll
        for (int kk = 0; kk < BK; kk++) {
            float a[4], bb[2];
            #pragma unroll
            for (int i = 0; i < 4; i++) a[i]  = As[kk][ty * 4 + i];
            #pragma unroll
            for (int j = 0; j < 2; j++) bb[j] = Bs[kk][tx * 2 + j];
            #pragma unroll
            for (int i = 0; i < 4; i++)
                #pragma unroll
                for (int j = 0; j < 2; j++)
                    acc[i][j] += a[i] * bb[j];
        }
        __syncthreads();
    }

    float* __restrict__ P = g_p1[z];
    #pragma unroll
    for (int i = 0; i < 4; i++) {
        const int mrow = m0 + ty * 4 + i;
        #pragma unroll
        for (int j = 0; j < 2; j++) {
            const int n = n0 + tx * 2 + j;
            P[(size_t)mrow * HID + n] = acc[i][j];
        }
    }
}

// ---------------------------------------------------------------------------
// Reduce split-K partials + bias + relu -> g_h1
// ---------------------------------------------------------------------------
__global__ __launch_bounds__(256) void reduce1_kernel(const float* __restrict__ bias) {
    const int idx = blockIdx.x * 256 + threadIdx.x;   // 0 .. BATCH*HID-1
    const int n = idx & (HID - 1);
    float v = bias[n];
    #pragma unroll
    for (int z = 0; z < KSPLIT; z++) v += g_p1[z][idx];
    g_h1[idx] = fmaxf(v, 0.f);
}

// ---------------------------------------------------------------------------
// Plain fused SGEMM (for layer 2, K=256): C = relu(A*W^T + bias)
// ---------------------------------------------------------------------------
__global__ __launch_bounds__(256) void gemm2_kernel(
    const float* __restrict__ A, const float* __restrict__ W,
    const float* __restrict__ bias, float* __restrict__ C)
{
    const int BM = 64, BN = 32, BK = 16, K = HID;
    __shared__ float As[BK][BM + 1];
    __shared__ float Bs[BK][BN + 1];

    const int t  = threadIdx.x;
    const int tx = t & 15;
    const int ty = t >> 4;
    const int m0 = blockIdx.x * BM;
    const int n0 = blockIdx.y * BN;

    const int a_mm = t >> 2;
    const int a_kk = (t & 3) * 4;

    float acc[4][2] = {};

    for (int k0 = 0; k0 < K; k0 += BK) {
        {
            float4 va = *(const float4*)&A[(size_t)(m0 + a_mm) * K + k0 + a_kk];
            As[a_kk + 0][a_mm] = va.x;
            As[a_kk + 1][a_mm] = va.y;
            As[a_kk + 2][a_mm] = va.z;
            As[a_kk + 3][a_mm] = va.w;
        }
        if (t < 128) {
            int nn = t >> 2;
            int kk = (t & 3) * 4;
            float4 vb = *(const float4*)&W[(size_t)(n0 + nn) * K + k0 + kk];
            Bs[kk + 0][nn] = vb.x;
            Bs[kk + 1][nn] = vb.y;
            Bs[kk + 2][nn] = vb.z;
            Bs[kk + 3][nn] = vb.w;
        }
        __syncthreads();

        #pragma unroll
        for (int kk = 0; kk < BK; kk++) {
            float a[4], bb[2];
            #pragma unroll
            for (int i = 0; i < 4; i++) a[i]  = As[kk][ty * 4 + i];
            #pragma unroll
            for (int j = 0; j < 2; j++) bb[j] = Bs[kk][tx * 2 + j];
            #pragma unroll
            for (int i = 0; i < 4; i++)
                #pragma unroll
                for (int j = 0; j < 2; j++)
                    acc[i][j] += a[i] * bb[j];
        }
        __syncthreads();
    }

    #pragma unroll
    for (int i = 0; i < 4; i++) {
        const int mrow = m0 + ty * 4 + i;
        #pragma unroll
        for (int j = 0; j < 2; j++) {
            const int n = n0 + tx * 2 + j;
            C[(size_t)mrow * HID + n] = fmaxf(acc[i][j] + bias[n], 0.f);
        }
    }
}

// ---------------------------------------------------------------------------
// out[b] = sigmoid(dot(h2[b,:], W3) + b3). One warp per row.
// ---------------------------------------------------------------------------
__global__ __launch_bounds__(256) void out_kernel(
    const float* __restrict__ W3, const float* __restrict__ b3,
    float* __restrict__ out)
{
    const int warp = (blockIdx.x * blockDim.x + threadIdx.x) >> 5;
    const int lane = threadIdx.x & 31;
    if (warp >= BATCH) return;
    const float* __restrict__ h = g_h2 + (size_t)warp * HID;
    float acc = 0.f;
    #pragma unroll
    for (int i = lane; i < HID; i += 32) acc += h[i] * W3[i];
    #pragma unroll
    for (int off = 16; off; off >>= 1)
        acc += __shfl_down_sync(0xffffffffu, acc, off);
    if (lane == 0) out[warp] = 1.f / (1.f + expf(-(acc + b3[0])));
}

// ---------------------------------------------------------------------------
extern "C" void kernel_launch(void* const* d_in, const int* in_sizes, int n_in,
                              void* d_out, int out_size)
{
    const float* x  = (const float*)d_in[0];
    const float* W1 = (const float*)d_in[1];
    const float* b1 = (const float*)d_in[2];
    const float* W2 = (const float*)d_in[3];
    const float* b2 = (const float*)d_in[4];
    const float* W3 = (const float*)d_in[5];
    const float* b3 = (const float*)d_in[6];
    float* out = (float*)d_out;

    float *p_h0, *p_w1f, *p_h1, *p_h2;
    cudaGetSymbolAddress((void**)&p_h0,  g_h0);
    cudaGetSymbolAddress((void**)&p_w1f, g_w1f);
    cudaGetSymbolAddress((void**)&p_h1,  g_h1);
    cudaGetSymbolAddress((void**)&p_h2,  g_h2);

    mean_kernel<<<BATCH * NFFT / 4 / 256, 256>>>(x);
    fold_w1_kernel<<<(HID * KF + 255) / 256, 256>>>(W1);
    fft_kernel<<<BATCH, 512>>>();

    dim3 g1(BATCH / 64, HID / 32, KSPLIT);   // (16, 8, 4) = 512 CTAs
    gemm_splitk_kernel<<<g1, 256>>>(p_h0, p_w1f);
    reduce1_kernel<<<BATCH * HID / 256, 256>>>(b1);

    dim3 g2(BATCH / 64, HID / 32);           // (16, 8) = 128 CTAs
    gemm2_kernel<<<g2, 256>>>(p_h1, W2, b2, p_h2);

    out_kernel<<<BATCH * 32 / 256, 256>>>(W3, b3, out);
}

// round 4
// speedup vs baseline: 2.4684x; 1.1202x over previous
#include <cuda_runtime.h>
#include <math.h>

#define BATCH 1024
#define FRAMES 31
#define NFFT 2048
#define N2 1024            // packed complex FFT length
#define KF 1088            // folded K: 1025 padded to 4*272 (272 = 17*16)
#define HID 256

// Scratch (allocation-free rule: __device__ globals)
__device__ __align__(16) float g_mean[BATCH * NFFT];       // 8 MB frame-mean
__device__ __align__(16) float g_h0[BATCH * KF];           // folded Re-spectrum
__device__ __align__(16) float g_w1f[HID * KF];            // folded W1
__device__ __align__(16) float g_p1[4][BATCH * HID];       // gemm1 split-K partials
__device__ __align__(16) float g_p2[2][BATCH * HID];       // gemm2 split-K partials
__device__ __align__(16) float g_h1[BATCH * HID];
__device__ __align__(16) float g_h2[BATCH * HID];

// ---------------------------------------------------------------------------
// Fold W1: W1f[n,k] = W1[n,k] + W1[n,2048-k] for 1<=k<=1023; ends unfolded;
// zero-pad cols 1025..KF-1.
// ---------------------------------------------------------------------------
__global__ __launch_bounds__(256) void fold_w1_kernel(const float* __restrict__ W1) {
    int idx = blockIdx.x * blockDim.x + threadIdx.x;
    if (idx >= HID * KF) return;
    int n = idx / KF;
    int k = idx - n * KF;
    float v;
    if (k == 0)             v = W1[(size_t)n * NFFT];
    else if (k < 1024)      v = W1[(size_t)n * NFFT + k] + W1[(size_t)n * NFFT + (NFFT - k)];
    else if (k == 1024)     v = W1[(size_t)n * NFFT + 1024];
    else                    v = 0.f;
    g_w1f[idx] = v;
}

// ---------------------------------------------------------------------------
// Pure-bandwidth frame mean: one float4 output per thread, 31 strided loads.
// ---------------------------------------------------------------------------
__global__ __launch_bounds__(256) void mean_kernel(const float* __restrict__ x) {
    const int idx = blockIdx.x * 256 + threadIdx.x;          // 0 .. 524287
    const int b   = idx >> 9;
    const int c   = idx & 511;
    const float4* __restrict__ p =
        (const float4*)x + (size_t)b * (FRAMES * NFFT / 4) + c;
    float4 acc = make_float4(0.f, 0.f, 0.f, 0.f);
    #pragma unroll
    for (int t = 0; t < FRAMES; t++) {
        float4 v = p[t * (NFFT / 4)];
        acc.x += v.x; acc.y += v.y; acc.z += v.z; acc.w += v.w;
    }
    const float inv = 1.0f / FRAMES;
    acc.x *= inv; acc.y *= inv; acc.z *= inv; acc.w *= inv;
    ((float4*)g_mean)[idx] = acc;
}

// ---------------------------------------------------------------------------
// Real-packed 1024-pt FFT + untangle. One block (512 thr) per batch row.
// ---------------------------------------------------------------------------
__global__ __launch_bounds__(512) void fft_kernel() {
    __shared__ float2 s[N2];        // 8 KB
    __shared__ float2 tw[N2 / 2];   // 4 KB

    const int b   = blockIdx.x;
    const int tid = threadIdx.x;
    const float2* __restrict__ m = (const float2*)g_mean + (size_t)b * N2;

    #pragma unroll
    for (int j = tid; j < N2; j += 512) {
        float2 v = m[j];
        unsigned r = __brev((unsigned)j) >> 22;
        s[r] = v;
    }
    if (tid < N2 / 2) {
        float sv, cv;
        sincosf(-6.28318530717958647692f * (float)tid * (1.0f / N2), &sv, &cv);
        tw[tid] = make_float2(cv, sv);
    }
    __syncthreads();

    #pragma unroll 1
    for (int st = 1; st <= 10; st++) {
        const int half = 1 << (st - 1);
        const int j    = tid & (half - 1);
        const int pos  = ((tid >> (st - 1)) << st) + j;
        const float2 w = tw[j << (10 - st)];
        const float2 u = s[pos];
        const float2 v = s[pos + half];
        const float vr = v.x * w.x - v.y * w.y;
        const float vi = v.x * w.y + v.y * w.x;
        s[pos]        = make_float2(u.x + vr, u.y + vi);
        s[pos + half] = make_float2(u.x - vr, u.y - vi);
        __syncthreads();
    }

    float* __restrict__ out = g_h0 + (size_t)b * KF;
    #pragma unroll 1
    for (int k = tid; k <= N2 / 2; k += 512) {
        const float2 zk = s[k];
        const float2 z2 = s[(N2 - k) & (N2 - 1)];
        float sn, cs;
        sincosf(3.14159265358979323846f * (float)k * (1.0f / N2), &sn, &cs);
        const float sumr = zk.x + z2.x;
        const float sumi = zk.y + z2.y;
        const float difr = zk.x - z2.x;
        out[k]      = 0.5f * (sumr + cs * sumi - sn * difr);
        out[N2 - k] = 0.5f * (sumr - cs * sumi + sn * difr);
    }
    for (int k = N2 + 1 + tid; k < KF; k += 512) out[k] = 0.f;
}

// ---------------------------------------------------------------------------
// Split-K SGEMM partial: P[z] += A[M, chunk] * W[N, chunk]^T
// BM=64, BN=64, BK=16, 128 threads, 8x4 thread tile, LDS.128 compute reads.
// KS = row stride of A and W; NITER = chunk/16.
// ---------------------------------------------------------------------------
template <int KS, int NITER>
__global__ __launch_bounds__(128) void gemm_splitk_kernel(
    const float* __restrict__ A, const float* __restrict__ W,
    float* __restrict__ Pbase)
{
    const int BM = 64, BN = 64;
    __shared__ float As[16][BM + 4];
    __shared__ float Bs[16][BN + 4];

    const int t  = threadIdx.x;          // 0..127
    const int tm = t >> 4;               // 0..7  (m-dir, x8)
    const int tn = t & 15;               // 0..15 (n-dir, x4)
    const int m0 = blockIdx.x * BM;
    const int n0 = blockIdx.y * BN;
    const int z  = blockIdx.z;
    const int kbeg = z * NITER * 16;

    float acc[8][4] = {};

    #pragma unroll 1
    for (int it = 0; it < NITER; it++) {
        const int k0 = kbeg + it * 16;
        // fill As (64m x 16k = 256 float4) and Bs, 2 float4 each per thread
        #pragma unroll
        for (int i = 0; i < 2; i++) {
            const int lin = t + i * 128;
            const int mm  = lin >> 2;
            const int kk  = (lin & 3) * 4;
            float4 va = *(const float4*)&A[(size_t)(m0 + mm) * KS + k0 + kk];
            As[kk + 0][mm] = va.x;
            As[kk + 1][mm] = va.y;
            As[kk + 2][mm] = va.z;
            As[kk + 3][mm] = va.w;
            float4 vb = *(const float4*)&W[(size_t)(n0 + mm) * KS + k0 + kk];
            Bs[kk + 0][mm] = vb.x;
            Bs[kk + 1][mm] = vb.y;
            Bs[kk + 2][mm] = vb.z;
            Bs[kk + 3][mm] = vb.w;
        }
        __syncthreads();

        #pragma unroll
        for (int kk = 0; kk < 16; kk++) {
            const float4 a0 = *(const float4*)&As[kk][tm * 8];
            const float4 a1 = *(const float4*)&As[kk][tm * 8 + 4];
            const float4 bb = *(const float4*)&Bs[kk][tn * 4];
            const float a[8] = {a0.x, a0.y, a0.z, a0.w, a1.x, a1.y, a1.z, a1.w};
            const float bv[4] = {bb.x, bb.y, bb.z, bb.w};
            #pragma unroll
            for (int i = 0; i < 8; i++)
                #pragma unroll
                for (int j = 0; j < 4; j++)
                    acc[i][j] += a[i] * bv[j];
        }
        __syncthreads();
    }

    float* __restrict__ P = Pbase + (size_t)z * (BATCH * HID);
    #pragma unroll
    for (int i = 0; i < 8; i++) {
        const int mrow = m0 + tm * 8 + i;
        float4 v = make_float4(acc[i][0], acc[i][1], acc[i][2], acc[i][3]);
        *(float4*)&P[(size_t)mrow * HID + n0 + tn * 4] = v;
    }
}

// ---------------------------------------------------------------------------
// Reduce split-K partials + bias + relu
// ---------------------------------------------------------------------------
template <int NZ>
__global__ __launch_bounds__(256) void reduce_kernel(
    const float* __restrict__ Pbase, const float* __restrict__ bias,
    float* __restrict__ out)
{
    const int idx = blockIdx.x * 256 + threadIdx.x;   // 0 .. BATCH*HID-1
    const int n = idx & (HID - 1);
    float v = bias[n];
    #pragma unroll
    for (int zz = 0; zz < NZ; zz++) v += Pbase[(size_t)zz * (BATCH * HID) + idx];
    out[idx] = fmaxf(v, 0.f);
}

// ---------------------------------------------------------------------------
// out[b] = sigmoid(dot(h2[b,:], W3) + b3). One warp per row.
// ---------------------------------------------------------------------------
__global__ __launch_bounds__(256) void out_kernel(
    const float* __restrict__ W3, const float* __restrict__ b3,
    float* __restrict__ out)
{
    const int warp = (blockIdx.x * blockDim.x + threadIdx.x) >> 5;
    const int lane = threadIdx.x & 31;
    if (warp >= BATCH) return;
    const float* __restrict__ h = g_h2 + (size_t)warp * HID;
    float acc = 0.f;
    #pragma unroll
    for (int i = lane; i < HID; i += 32) acc += h[i] * W3[i];
    #pragma unroll
    for (int off = 16; off; off >>= 1)
        acc += __shfl_down_sync(0xffffffffu, acc, off);
    if (lane == 0) out[warp] = 1.f / (1.f + expf(-(acc + b3[0])));
}

// ---------------------------------------------------------------------------
extern "C" void kernel_launch(void* const* d_in, const int* in_sizes, int n_in,
                              void* d_out, int out_size)
{
    const float* x  = (const float*)d_in[0];
    const float* W1 = (const float*)d_in[1];
    const float* b1 = (const float*)d_in[2];
    const float* W2 = (const float*)d_in[3];
    const float* b2 = (const float*)d_in[4];
    const float* W3 = (const float*)d_in[5];
    const float* b3 = (const float*)d_in[6];
    float* out = (float*)d_out;

    float *p_h0, *p_w1f, *p_h1, *p_h2, *p_p1, *p_p2;
    cudaGetSymbolAddress((void**)&p_h0,  g_h0);
    cudaGetSymbolAddress((void**)&p_w1f, g_w1f);
    cudaGetSymbolAddress((void**)&p_h1,  g_h1);
    cudaGetSymbolAddress((void**)&p_h2,  g_h2);
    cudaGetSymbolAddress((void**)&p_p1,  g_p1);
    cudaGetSymbolAddress((void**)&p_p2,  g_p2);

    mean_kernel<<<BATCH * NFFT / 4 / 256, 256>>>(x);
    fold_w1_kernel<<<(HID * KF + 255) / 256, 256>>>(W1);
    fft_kernel<<<BATCH, 512>>>();

    // layer 1: K=1088, split 4 x 272 -> (16,4,4) = 256 CTAs
    dim3 g1(BATCH / 64, HID / 64, 4);
    gemm_splitk_kernel<KF, 17><<<g1, 128>>>(p_h0, p_w1f, p_p1);
    reduce_kernel<4><<<BATCH * HID / 256, 256>>>(p_p1, b1, p_h1);

    // layer 2: K=256, split 2 x 128 -> (16,4,2) = 128 CTAs
    dim3 g2(BATCH / 64, HID / 64, 2);
    gemm_splitk_kernel<HID, 8><<<g2, 128>>>(p_h1, W2, p_p2);
    reduce_kernel<2><<<BATCH * HID / 256, 256>>>(p_p2, b2, p_h2);

    out_kernel<<<BATCH * 32 / 256, 256>>>(W3, b3, out);
}

// round 5
// speedup vs baseline: 2.7567x; 1.1168x over previous
#include <cuda_runtime.h>
#include <math.h>

#define BATCH 1024
#define FRAMES 31
#define NFFT 2048
#define N2 1024            // packed complex FFT length
#define KF 1152            // folded K: 1025 padded to 8*144 (144 = 9*16)
#define HID 256

// Scratch (allocation-free rule: __device__ globals)
__device__ __align__(16) float g_h0[BATCH * KF];           // folded Re-spectrum
__device__ __align__(16) float g_w1f[HID * KF];            // folded W1
__device__ __align__(16) float2 g_tw[N2];                  // exp(-2*pi*i*a/1024)
__device__ __align__(16) float2 g_unt[N2 / 2 + 1];         // (cos,sin)(pi*k/1024)
__device__ __align__(16) float g_p1[8][BATCH * HID];       // gemm1 split-K partials
__device__ __align__(16) float g_p2[2][BATCH * HID];       // gemm2 split-K partials
__device__ __align__(16) float g_h1[BATCH * HID];

// ---------------------------------------------------------------------------
// Init: twiddle table (full 1024) + untangle table (513). One block.
// ---------------------------------------------------------------------------
__global__ __launch_bounds__(512) void tables_kernel() {
    const int tid = threadIdx.x;
    for (int a = tid; a < N2; a += 512) {
        float sv, cv;
        sincosf(-6.28318530717958647692f * (float)a * (1.0f / N2), &sv, &cv);
        g_tw[a] = make_float2(cv, sv);
    }
    for (int k = tid; k <= N2 / 2; k += 512) {
        float sv, cv;
        sincosf(3.14159265358979323846f * (float)k * (1.0f / N2), &sv, &cv);
        g_unt[k] = make_float2(cv, sv);
    }
}

// ---------------------------------------------------------------------------
// Fold W1: W1f[n,k] = W1[n,k] + W1[n,2048-k] (ends unfolded), pad to KF.
// ---------------------------------------------------------------------------
__global__ __launch_bounds__(256) void fold_w1_kernel(const float* __restrict__ W1) {
    int idx = blockIdx.x * blockDim.x + threadIdx.x;
    if (idx >= HID * KF) return;
    int n = idx / KF;
    int k = idx - n * KF;
    float v;
    if (k == 0)             v = W1[(size_t)n * NFFT];
    else if (k < 1024)      v = W1[(size_t)n * NFFT + k] + W1[(size_t)n * NFFT + (NFFT - k)];
    else if (k == 1024)     v = W1[(size_t)n * NFFT + 1024];
    else                    v = 0.f;
    g_w1f[idx] = v;
}

// ---------------------------------------------------------------------------
// Fused frame-mean + real-packed 1024-pt radix-4 FFT + untangle.
// One block (256 thr) per batch row; 6+ blocks/SM so DRAM streaming of other
// blocks overlaps this block's FFT stages.
// ---------------------------------------------------------------------------
__device__ __forceinline__ unsigned rev4_10(unsigned j) {
    unsigned r = __brev(j) >> 22;                       // 10-bit bit reversal
    return ((r & 0x155u) << 1) | ((r >> 1) & 0x155u);   // swap bit pairs -> base-4
}

__global__ __launch_bounds__(256, 6) void fftmean_kernel(const float* __restrict__ x) {
    __shared__ float2 s[N2];        // 8 KB
    __shared__ float2 tw[N2];       // 8 KB

    const int b   = blockIdx.x;
    const int tid = threadIdx.x;
    const float4* __restrict__ p = (const float4*)x + (size_t)b * (FRAMES * NFFT / 4);

    // twiddles from global (L2-resident)
    #pragma unroll
    for (int a = tid; a < N2; a += 256) tw[a] = g_tw[a];

    // frame mean: two float4 per thread, sequential to bound reg pressure
    const float inv = 1.0f / FRAMES;
    #pragma unroll
    for (int h = 0; h < 2; h++) {
        const int f = tid + h * 256;                    // float4 index in row
        float4 acc = make_float4(0.f, 0.f, 0.f, 0.f);
        #pragma unroll
        for (int t = 0; t < FRAMES; t++) {
            float4 v = p[f + t * (NFFT / 4)];
            acc.x += v.x; acc.y += v.y; acc.z += v.z; acc.w += v.w;
        }
        // z[2f] = (x,y), z[2f+1] = (z,w), stored base-4 digit-reversed
        s[rev4_10(2 * f)]     = make_float2(acc.x * inv, acc.y * inv);
        s[rev4_10(2 * f + 1)] = make_float2(acc.z * inv, acc.w * inv);
    }
    __syncthreads();

    // 5 radix-4 DIT stages, one butterfly (4 points) per thread per stage
    #pragma unroll
    for (int st = 0; st < 5; st++) {
        const int q    = 1 << (2 * st);          // 4^st
        const int j    = tid & (q - 1);
        const int blk  = tid >> (2 * st);
        const int base = (blk << (2 * st + 2)) + j;
        const int e    = j << (8 - 2 * st);      // j * (N/L), L = 4q

        float2 x0 = s[base];
        float2 x1 = s[base + q];
        float2 x2 = s[base + 2 * q];
        float2 x3 = s[base + 3 * q];
        if (e) {                                  // e==0 only when j==0
            const float2 w1 = tw[e], w2 = tw[2 * e], w3 = tw[3 * e];
            x1 = make_float2(x1.x * w1.x - x1.y * w1.y, x1.x * w1.y + x1.y * w1.x);
            x2 = make_float2(x2.x * w2.x - x2.y * w2.y, x2.x * w2.y + x2.y * w2.x);
            x3 = make_float2(x3.x * w3.x - x3.y * w3.y, x3.x * w3.y + x3.y * w3.x);
        }
        const float2 ap = make_float2(x0.x + x2.x, x0.y + x2.y);
        const float2 am = make_float2(x0.x - x2.x, x0.y - x2.y);
        const float2 bp = make_float2(x1.x + x3.x, x1.y + x3.y);
        const float2 bm = make_float2(x1.x - x3.x, x1.y - x3.y);
        __syncthreads();   // protect reads above from writes below across threads? no:
        // NOTE: reads and writes are to the same 4 slots per thread (in-place,
        // disjoint across threads), so no barrier needed between them; the
        // barrier orders THIS stage's writes before NEXT stage's reads.
        s[base]         = make_float2(ap.x + bp.x, ap.y + bp.y);
        s[base + q]     = make_float2(am.x + bm.y, am.y - bm.x);   // am - i*bm
        s[base + 2 * q] = make_float2(ap.x - bp.x, ap.y - bp.y);
        s[base + 3 * q] = make_float2(am.x - bm.y, am.y + bm.x);   // am + i*bm
        __syncthreads();
    }

    // untangle: Re X[k], Re X[1024-k] from Z[k], Z[(1024-k)&1023]
    float* __restrict__ out = g_h0 + (size_t)b * KF;
    #pragma unroll
    for (int k = tid; k <= N2 / 2; k += 256) {
        const float2 zk = s[k];
        const float2 z2 = s[(N2 - k) & (N2 - 1)];
        const float2 u  = g_unt[k];
        const float sumr = zk.x + z2.x;
        const float sumi = zk.y + z2.y;
        const float difr = zk.x - z2.x;
        out[k]      = 0.5f * (sumr + u.x * sumi - u.y * difr);
        out[N2 - k] = 0.5f * (sumr - u.x * sumi + u.y * difr);
    }
    for (int k = N2 + 1 + tid; k < KF; k += 256) out[k] = 0.f;   // pad 1025..1151
}

// ---------------------------------------------------------------------------
// Split-K SGEMM partial, double-buffered: P[z] = A[M,chunk] * W[N,chunk]^T
// BM=64, BN=64, BK=16, 128 threads, 8x4 thread tile, LDS.128 compute reads.
// ---------------------------------------------------------------------------
template <int KS, int NITER>
__global__ __launch_bounds__(128) void gemm_splitk_kernel(
    const float* __restrict__ A, const float* __restrict__ W,
    float* __restrict__ Pbase)
{
    const int BM = 64, BN = 64;
    __shared__ float As[2][16][BM + 4];
    __shared__ float Bs[2][16][BN + 4];

    const int t  = threadIdx.x;          // 0..127
    const int tm = t >> 4;               // 0..7  (m-dir, x8)
    const int tn = t & 15;               // 0..15 (n-dir, x4)
    const int m0 = blockIdx.x * BM;
    const int n0 = blockIdx.y * BN;
    const int z  = blockIdx.z;
    const int kbeg = z * NITER * 16;

    // fill coords: 2 float4 per array per thread
    const int mmA = t >> 2;              // 0..31  (+32 for second)
    const int kkA = (t & 3) * 4;

    float acc[8][4] = {};
    float4 ra0, ra1, rb0, rb1;

    // preload tile 0
    {
        const int k0 = kbeg;
        ra0 = *(const float4*)&A[(size_t)(m0 + mmA)      * KS + k0 + kkA];
        ra1 = *(const float4*)&A[(size_t)(m0 + mmA + 32) * KS + k0 + kkA];
        rb0 = *(const float4*)&W[(size_t)(n0 + mmA)      * KS + k0 + kkA];
        rb1 = *(const float4*)&W[(size_t)(n0 + mmA + 32) * KS + k0 + kkA];
        As[0][kkA + 0][mmA] = ra0.x; As[0][kkA + 1][mmA] = ra0.y;
        As[0][kkA + 2][mmA] = ra0.z; As[0][kkA + 3][mmA] = ra0.w;
        As[0][kkA + 0][mmA + 32] = ra1.x; As[0][kkA + 1][mmA + 32] = ra1.y;
        As[0][kkA + 2][mmA + 32] = ra1.z; As[0][kkA + 3][mmA + 32] = ra1.w;
        Bs[0][kkA + 0][mmA] = rb0.x; Bs[0][kkA + 1][mmA] = rb0.y;
        Bs[0][kkA + 2][mmA] = rb0.z; Bs[0][kkA + 3][mmA] = rb0.w;
        Bs[0][kkA + 0][mmA + 32] = rb1.x; Bs[0][kkA + 1][mmA + 32] = rb1.y;
        Bs[0][kkA + 2][mmA + 32] = rb1.z; Bs[0][kkA + 3][mmA + 32] = rb1.w;
    }

    #pragma unroll 1
    for (int it = 0; it < NITER; it++) {
        const int cur = it & 1;
        __syncthreads();
        if (it + 1 < NITER) {
            const int k0 = kbeg + (it + 1) * 16;
            ra0 = *(const float4*)&A[(size_t)(m0 + mmA)      * KS + k0 + kkA];
            ra1 = *(const float4*)&A[(size_t)(m0 + mmA + 32) * KS + k0 + kkA];
            rb0 = *(const float4*)&W[(size_t)(n0 + mmA)      * KS + k0 + kkA];
            rb1 = *(const float4*)&W[(size_t)(n0 + mmA + 32) * KS + k0 + kkA];
        }

        #pragma unroll
        for (int kk = 0; kk < 16; kk++) {
            const float4 a0 = *(const float4*)&As[cur][kk][tm * 8];
            const float4 a1 = *(const float4*)&As[cur][kk][tm * 8 + 4];
            const float4 bb = *(const float4*)&Bs[cur][kk][tn * 4];
            const float a[8] = {a0.x, a0.y, a0.z, a0.w, a1.x, a1.y, a1.z, a1.w};
            const float bv[4] = {bb.x, bb.y, bb.z, bb.w};
            #pragma unroll
            for (int i = 0; i < 8; i++)
                #pragma unroll
                for (int j = 0; j < 4; j++)
                    acc[i][j] += a[i] * bv[j];
        }

        if (it + 1 < NITER) {
            const int nxt = cur ^ 1;
            As[nxt][kkA + 0][mmA] = ra0.x; As[nxt][kkA + 1][mmA] = ra0.y;
            As[nxt][kkA + 2][mmA] = ra0.z; As[nxt][kkA + 3][mmA] = ra0.w;
            As[nxt][kkA + 0][mmA + 32] = ra1.x; As[nxt][kkA + 1][mmA + 32] = ra1.y;
            As[nxt][kkA + 2][mmA + 32] = ra1.z; As[nxt][kkA + 3][mmA + 32] = ra1.w;
            Bs[nxt][kkA + 0][mmA] = rb0.x; Bs[nxt][kkA + 1][mmA] = rb0.y;
            Bs[nxt][kkA + 2][mmA] = rb0.z; Bs[nxt][kkA + 3][mmA] = rb0.w;
            Bs[nxt][kkA + 0][mmA + 32] = rb1.x; Bs[nxt][kkA + 1][mmA + 32] = rb1.y;
            Bs[nxt][kkA + 2][mmA + 32] = rb1.z; Bs[nxt][kkA + 3][mmA + 32] = rb1.w;
        }
    }

    float* __restrict__ P = Pbase + (size_t)z * (BATCH * HID);
    #pragma unroll
    for (int i = 0; i < 8; i++) {
        const int mrow = m0 + tm * 8 + i;
        float4 v = make_float4(acc[i][0], acc[i][1], acc[i][2], acc[i][3]);
        *(float4*)&P[(size_t)mrow * HID + n0 + tn * 4] = v;
    }
}

// ---------------------------------------------------------------------------
// Reduce gemm1 partials + bias + relu -> g_h1
// ---------------------------------------------------------------------------
__global__ __launch_bounds__(256) void reduce1_kernel(const float* __restrict__ bias) {
    const int idx = blockIdx.x * 256 + threadIdx.x;
    const int n = idx & (HID - 1);
    float v = bias[n];
    #pragma unroll
    for (int zz = 0; zz < 8; zz++) v += g_p1[zz][idx];
    g_h1[idx] = fmaxf(v, 0.f);
}

// ---------------------------------------------------------------------------
// Fused: reduce gemm2 partials + bias + relu + dot(W3) + sigmoid -> out
// One block (256 thr) per batch row.
// ---------------------------------------------------------------------------
__global__ __launch_bounds__(256) void reduce2_out_kernel(
    const float* __restrict__ b2, const float* __restrict__ W3,
    const float* __restrict__ b3, float* __restrict__ out)
{
    __shared__ float red[8];
    const int b = blockIdx.x;
    const int n = threadIdx.x;
    const int idx = b * HID + n;
    float v = b2[n] + g_p2[0][idx] + g_p2[1][idx];
    v = fmaxf(v, 0.f) * W3[n];
    #pragma unroll
    for (int off = 16; off; off >>= 1) v += __shfl_down_sync(0xffffffffu, v, off);
    if ((n & 31) == 0) red[n >> 5] = v;
    __syncthreads();
    if (n == 0) {
        float s = 0.f;
        #pragma unroll
        for (int w = 0; w < 8; w++) s += red[w];
        out[b] = 1.f / (1.f + expf(-(s + b3[0])));
    }
}

// ---------------------------------------------------------------------------
extern "C" void kernel_launch(void* const* d_in, const int* in_sizes, int n_in,
                              void* d_out, int out_size)
{
    const float* x  = (const float*)d_in[0];
    const float* W1 = (const float*)d_in[1];
    const float* b1 = (const float*)d_in[2];
    const float* W2 = (const float*)d_in[3];
    const float* b2 = (const float*)d_in[4];
    const float* W3 = (const float*)d_in[5];
    const float* b3 = (const float*)d_in[6];
    float* out = (float*)d_out;

    float *p_h0, *p_w1f, *p_h1, *p_p1, *p_p2;
    cudaGetSymbolAddress((void**)&p_h0,  g_h0);
    cudaGetSymbolAddress((void**)&p_w1f, g_w1f);
    cudaGetSymbolAddress((void**)&p_h1,  g_h1);
    cudaGetSymbolAddress((void**)&p_p1,  g_p1);
    cudaGetSymbolAddress((void**)&p_p2,  g_p2);

    tables_kernel<<<1, 512>>>();
    fold_w1_kernel<<<HID * KF / 256, 256>>>(W1);
    fftmean_kernel<<<BATCH, 256>>>(x);

    // layer 1: K=1152, split 8 x 144 -> (16,4,8) = 512 CTAs
    dim3 g1(BATCH / 64, HID / 64, 8);
    gemm_splitk_kernel<KF, 9><<<g1, 128>>>(p_h0, p_w1f, p_p1);
    reduce1_kernel<<<BATCH * HID / 256, 256>>>(b1);

    // layer 2: K=256, split 2 x 128 -> (16,4,2) = 128 CTAs
    dim3 g2(BATCH / 64, HID / 64, 2);
    gemm_splitk_kernel<HID, 8><<<g2, 128>>>(p_h1, W2, p_p2);

    reduce2_out_kernel<<<BATCH, 256>>>(b2, W3, b3, out);
}

// round 7
// speedup vs baseline: 2.9008x; 1.0523x over previous
#include <cuda_runtime.h>
#include <cuda_bf16.h>
#include <math.h>
#include <stdint.h>

#define BATCH 1024
#define FRAMES 31
#define NFFT 2048
#define N2 1024            // packed complex FFT length
#define KF 1152            // folded K: 1025 padded to 3*384
#define HID 256
#define NZ1 9              // gemm1 z: 3 terms x 3 k-chunks
#define KCH1 384
#define ASTR 40            // smem row stride (bf16 elems): 32 + 8 pad

// Scratch (allocation-free rule: __device__ globals)
__device__ __align__(16) __nv_bfloat16 g_a_h[BATCH * KF];
__device__ __align__(16) __nv_bfloat16 g_a_l[BATCH * KF];
__device__ __align__(16) __nv_bfloat16 g_w_h[HID * KF];
__device__ __align__(16) __nv_bfloat16 g_w_l[HID * KF];
__device__ __align__(16) float2 g_tw[N2];
__device__ __align__(16) float2 g_unt[N2 / 2 + 1];
__device__ __align__(16) float g_p1[NZ1][BATCH * HID];
__device__ __align__(16) float g_p2[2][BATCH * HID];
__device__ __align__(16) float g_h1[BATCH * HID];

// ---------------------------------------------------------------------------
// helpers
// ---------------------------------------------------------------------------
__device__ __forceinline__ uint32_t s2u(const void* p) {
    uint32_t a;
    asm("{ .reg .u64 t; cvta.to.shared.u64 t, %1; cvt.u32.u64 %0, t; }"
        : "=r"(a) : "l"(p));
    return a;
}
__device__ __forceinline__ void ldsm4(uint32_t& r0, uint32_t& r1, uint32_t& r2,
                                      uint32_t& r3, uint32_t addr) {
    asm volatile("ldmatrix.sync.aligned.m8n8.x4.shared.b16 {%0,%1,%2,%3}, [%4];"
                 : "=r"(r0), "=r"(r1), "=r"(r2), "=r"(r3) : "r"(addr));
}
__device__ __forceinline__ void ldsm2(uint32_t& r0, uint32_t& r1, uint32_t addr) {
    asm volatile("ldmatrix.sync.aligned.m8n8.x2.shared.b16 {%0,%1}, [%2];"
                 : "=r"(r0), "=r"(r1) : "r"(addr));
}
__device__ __forceinline__ void mma_bf16(float* d, const uint32_t* a, const uint32_t* b) {
    asm volatile(
        "mma.sync.aligned.m16n8k16.row.col.f32.bf16.bf16.f32 "
        "{%0,%1,%2,%3}, {%4,%5,%6,%7}, {%8,%9}, {%0,%1,%2,%3};"
        : "+f"(d[0]), "+f"(d[1]), "+f"(d[2]), "+f"(d[3])
        : "r"(a[0]), "r"(a[1]), "r"(a[2]), "r"(a[3]), "r"(b[0]), "r"(b[1]));
}
__device__ __forceinline__ void bf_split(float v, __nv_bfloat16& h, __nv_bfloat16& l) {
    h = __float2bfloat16(v);
    l = __float2bfloat16(v - __bfloat162float(h));
}

// ---------------------------------------------------------------------------
// Init: twiddle table (1024) + untangle table (513).
// ---------------------------------------------------------------------------
__global__ __launch_bounds__(512) void tables_kernel() {
    const int tid = threadIdx.x;
    for (int a = tid; a < N2; a += 512) {
        float sv, cv;
        sincosf(-6.28318530717958647692f * (float)a * (1.0f / N2), &sv, &cv);
        g_tw[a] = make_float2(cv, sv);
    }
    for (int k = tid; k <= N2 / 2; k += 512) {
        float sv, cv;
        sincosf(3.14159265358979323846f * (float)k * (1.0f / N2), &sv, &cv);
        g_unt[k] = make_float2(cv, sv);
    }
}

// ---------------------------------------------------------------------------
// Fold W1 + bf16 hi/lo split.
// ---------------------------------------------------------------------------
__global__ __launch_bounds__(256) void fold_w1_kernel(const float* __restrict__ W1) {
    int idx = blockIdx.x * blockDim.x + threadIdx.x;
    if (idx >= HID * KF) return;
    int n = idx / KF;
    int k = idx - n * KF;
    float v;
    if (k == 0)             v = W1[(size_t)n * NFFT];
    else if (k < 1024)      v = W1[(size_t)n * NFFT + k] + W1[(size_t)n * NFFT + (NFFT - k)];
    else if (k == 1024)     v = W1[(size_t)n * NFFT + 1024];
    else                    v = 0.f;
    __nv_bfloat16 h, l;
    bf_split(v, h, l);
    g_w_h[idx] = h;
    g_w_l[idx] = l;
}

// ---------------------------------------------------------------------------
// Fused frame-mean + real-packed 1024-pt radix-4 FFT + untangle -> bf16 hi/lo.
// ---------------------------------------------------------------------------
__device__ __forceinline__ unsigned rev4_10(unsigned j) {
    unsigned r = __brev(j) >> 22;
    return ((r & 0x155u) << 1) | ((r >> 1) & 0x155u);
}

__global__ __launch_bounds__(256, 6) void fftmean_kernel(const float* __restrict__ x) {
    __shared__ float2 s[N2];        // 8 KB
    __shared__ float2 tw[N2];       // 8 KB

    const int b   = blockIdx.x;
    const int tid = threadIdx.x;
    const float4* __restrict__ p = (const float4*)x + (size_t)b * (FRAMES * NFFT / 4);

    #pragma unroll
    for (int a = tid; a < N2; a += 256) tw[a] = g_tw[a];

    const float inv = 1.0f / FRAMES;
    #pragma unroll
    for (int h = 0; h < 2; h++) {
        const int f = tid + h * 256;
        float4 acc = make_float4(0.f, 0.f, 0.f, 0.f);
        #pragma unroll
        for (int t = 0; t < FRAMES; t++) {
            float4 v = p[f + t * (NFFT / 4)];
            acc.x += v.x; acc.y += v.y; acc.z += v.z; acc.w += v.w;
        }
        s[rev4_10(2 * f)]     = make_float2(acc.x * inv, acc.y * inv);
        s[rev4_10(2 * f + 1)] = make_float2(acc.z * inv, acc.w * inv);
    }
    __syncthreads();

    #pragma unroll
    for (int st = 0; st < 5; st++) {
        const int q    = 1 << (2 * st);
        const int j    = tid & (q - 1);
        const int blk  = tid >> (2 * st);
        const int base = (blk << (2 * st + 2)) + j;
        const int e    = j << (8 - 2 * st);

        float2 x0 = s[base];
        float2 x1 = s[base + q];
        float2 x2 = s[base + 2 * q];
        float2 x3 = s[base + 3 * q];
        if (e) {
            const float2 w1 = tw[e], w2 = tw[2 * e], w3 = tw[3 * e];
            x1 = make_float2(x1.x * w1.x - x1.y * w1.y, x1.x * w1.y + x1.y * w1.x);
            x2 = make_float2(x2.x * w2.x - x2.y * w2.y, x2.x * w2.y + x2.y * w2.x);
            x3 = make_float2(x3.x * w3.x - x3.y * w3.y, x3.x * w3.y + x3.y * w3.x);
        }
        const float2 ap = make_float2(x0.x + x2.x, x0.y + x2.y);
        const float2 am = make_float2(x0.x - x2.x, x0.y - x2.y);
        const float2 bp = make_float2(x1.x + x3.x, x1.y + x3.y);
        const float2 bm = make_float2(x1.x - x3.x, x1.y - x3.y);
        s[base]         = make_float2(ap.x + bp.x, ap.y + bp.y);
        s[base + q]     = make_float2(am.x + bm.y, am.y - bm.x);
        s[base + 2 * q] = make_float2(ap.x - bp.x, ap.y - bp.y);
        s[base + 3 * q] = make_float2(am.x - bm.y, am.y + bm.x);
        __syncthreads();
    }

    __nv_bfloat16* __restrict__ oh = g_a_h + (size_t)b * KF;
    __nv_bfloat16* __restrict__ ol = g_a_l + (size_t)b * KF;
    #pragma unroll
    for (int k = tid; k <= N2 / 2; k += 256) {
        const float2 zk = s[k];
        const float2 z2 = s[(N2 - k) & (N2 - 1)];
        const float2 u  = g_unt[k];
        const float sumr = zk.x + z2.x;
        const float sumi = zk.y + z2.y;
        const float difr = zk.x - z2.x;
        float v0 = 0.5f * (sumr + u.x * sumi - u.y * difr);
        float v1 = 0.5f * (sumr - u.x * sumi + u.y * difr);
        __nv_bfloat16 h, l;
        bf_split(v0, h, l); oh[k] = h;       ol[k] = l;
        bf_split(v1, h, l); oh[N2 - k] = h;  ol[N2 - k] = l;
    }
    const __nv_bfloat16 z16 = __float2bfloat16(0.f);
    for (int k = N2 + 1 + tid; k < KF; k += 256) { oh[k] = z16; ol[k] = z16; }
}

// ---------------------------------------------------------------------------
// GEMM1 via mma.sync bf16 (hi/lo 3-term), split-K.
// BM=128, BN=64, BK=32, 256 threads (8 warps, warp tile 64x16).
// grid (8, 4, 9): z = term*3 + kchunk; chunk = 384 cols (12 k-iters).
// ---------------------------------------------------------------------------
__global__ __launch_bounds__(256) void gemm1_mma_kernel() {
    __shared__ __nv_bfloat16 As[2][128 * ASTR];   // 20 KB
    __shared__ __nv_bfloat16 Bs[2][64 * ASTR];    // 10 KB

    const int tid  = threadIdx.x;
    const int wid  = tid >> 5;
    const int lane = tid & 31;
    const int wm0  = (wid & 1) * 64;     // warp m offset in block
    const int wn0  = (wid >> 1) * 16;    // warp n offset in block
    const int m0   = blockIdx.x * 128;
    const int n0   = blockIdx.y * 64;
    const int z    = blockIdx.z;
    const int term = z / 3;
    const int kbeg = (z - term * 3) * KCH1;

    const __nv_bfloat16* __restrict__ A = (term == 1) ? g_a_l : g_a_h;
    const __nv_bfloat16* __restrict__ W = (term == 2) ? g_w_l : g_w_h;

    // fill coords
    const int fr = tid >> 2;             // 0..63
    const int fc = (tid & 3) * 8;        // 0,8,16,24 (bf16 elems)

    // ldmatrix lane addressing
    const int a_row = (lane & 7) + ((lane >> 3) & 1) * 8;   // 0..15
    const int a_col = (lane >> 4) * 8;                       // 0 or 8
    const int lb    = lane & 15;
    const int b_row = lb & 7;                                // 0..7
    const int b_col = (lb >> 3) * 8;                         // 0 or 8

    float acc[4][2][4] = {};
    uint4 rA0, rA1, rB;

    // preload tile 0 into smem
    {
        const int k0 = kbeg;
        uint4 a0 = *(const uint4*)&A[(size_t)(m0 + fr)      * KF + k0 + fc];
        uint4 a1 = *(const uint4*)&A[(size_t)(m0 + fr + 64) * KF + k0 + fc];
        uint4 b0 = *(const uint4*)&W[(size_t)(n0 + fr)      * KF + k0 + fc];
        *(uint4*)&As[0][fr * ASTR + fc]        = a0;
        *(uint4*)&As[0][(fr + 64) * ASTR + fc] = a1;
        *(uint4*)&Bs[0][fr * ASTR + fc]        = b0;
    }

    #pragma unroll 1
    for (int it = 0; it < KCH1 / 32; it++) {
        const int cur = it & 1;
        __syncthreads();
        if (it + 1 < KCH1 / 32) {
            const int k0 = kbeg + (it + 1) * 32;
            rA0 = *(const uint4*)&A[(size_t)(m0 + fr)      * KF + k0 + fc];
            rA1 = *(const uint4*)&A[(size_t)(m0 + fr + 64) * KF + k0 + fc];
            rB  = *(const uint4*)&W[(size_t)(n0 + fr)      * KF + k0 + fc];
        }

        const uint32_t baseA = s2u(&As[cur][0]);
        const uint32_t baseB = s2u(&Bs[cur][0]);
        #pragma unroll
        for (int kk = 0; kk < 2; kk++) {
            uint32_t bfr[2][2];
            #pragma unroll
            for (int ni = 0; ni < 2; ni++) {
                uint32_t addr = baseB +
                    (uint32_t)(((wn0 + ni * 8 + b_row) * ASTR + kk * 16 + b_col) * 2);
                ldsm2(bfr[ni][0], bfr[ni][1], addr);
            }
            #pragma unroll
            for (int mi = 0; mi < 4; mi++) {
                uint32_t afr[4];
                uint32_t addr = baseA +
                    (uint32_t)(((wm0 + mi * 16 + a_row) * ASTR + kk * 16 + a_col) * 2);
                ldsm4(afr[0], afr[1], afr[2], afr[3], addr);
                mma_bf16(acc[mi][0], afr, bfr[0]);
                mma_bf16(acc[mi][1], afr, bfr[1]);
            }
        }

        if (it + 1 < KCH1 / 32) {
            const int nxt = cur ^ 1;
            *(uint4*)&As[nxt][fr * ASTR + fc]        = rA0;
            *(uint4*)&As[nxt][(fr + 64) * ASTR + fc] = rA1;
            *(uint4*)&Bs[nxt][fr * ASTR + fc]        = rB;
        }
    }

    // epilogue -> partial buffer
    float* __restrict__ P = g_p1[z];
    const int t4  = lane >> 2;
    const int t2  = (lane & 3) * 2;
    #pragma unroll
    for (int mi = 0; mi < 4; mi++) {
        const int row = m0 + wm0 + mi * 16 + t4;
        #pragma unroll
        for (int ni = 0; ni < 2; ni++) {
            const int col = n0 + wn0 + ni * 8 + t2;
            *(float2*)&P[(size_t)row * HID + col] =
                make_float2(acc[mi][ni][0], acc[mi][ni][1]);
            *(float2*)&P[(size_t)(row + 8) * HID + col] =
                make_float2(acc[mi][ni][2], acc[mi][ni][3]);
        }
    }
}

// ---------------------------------------------------------------------------
// Reduce gemm1 partials + bias + relu -> g_h1 (fp32)
// ---------------------------------------------------------------------------
__global__ __launch_bounds__(256) void reduce1_kernel(const float* __restrict__ bias) {
    const int idx = blockIdx.x * 256 + threadIdx.x;
    const int n = idx & (HID - 1);
    float v = bias[n];
    #pragma unroll
    for (int zz = 0; zz < NZ1; zz++) v += g_p1[zz][idx];
    g_h1[idx] = fmaxf(v, 0.f);
}

// ---------------------------------------------------------------------------
// fp32 split-K SGEMM for layer 2 (K=256), double-buffered.
// ---------------------------------------------------------------------------
template <int KS, int NITER>
__global__ __launch_bounds__(128) void gemm_splitk_kernel(
    const float* __restrict__ A, const float* __restrict__ W,
    float* __restrict__ Pbase)
{
    const int BM = 64, BN = 64;
    __shared__ float As[2][16][BM + 4];
    __shared__ float Bs[2][16][BN + 4];

    const int t  = threadIdx.x;
    const int tm = t >> 4;
    const int tn = t & 15;
    const int m0 = blockIdx.x * BM;
    const int n0 = blockIdx.y * BN;
    const int z  = blockIdx.z;
    const int kbeg = z * NITER * 16;

    const int mmA = t >> 2;
    const int kkA = (t & 3) * 4;

    float acc[8][4] = {};
    float4 ra0, ra1, rb0, rb1;

    {
        const int k0 = kbeg;
        ra0 = *(const float4*)&A[(size_t)(m0 + mmA)      * KS + k0 + kkA];
        ra1 = *(const float4*)&A[(size_t)(m0 + mmA + 32) * KS + k0 + kkA];
        rb0 = *(const float4*)&W[(size_t)(n0 + mmA)      * KS + k0 + kkA];
        rb1 = *(const float4*)&W[(size_t)(n0 + mmA + 32) * KS + k0 + kkA];
        As[0][kkA + 0][mmA] = ra0.x; As[0][kkA + 1][mmA] = ra0.y;
        As[0][kkA + 2][mmA] = ra0.z; As[0][kkA + 3][mmA] = ra0.w;
        As[0][kkA + 0][mmA + 32] = ra1.x; As[0][kkA + 1][mmA + 32] = ra1.y;
        As[0][kkA + 2][mmA + 32] = ra1.z; As[0][kkA + 3][mmA + 32] = ra1.w;
        Bs[0][kkA + 0][mmA] = rb0.x; Bs[0][kkA + 1][mmA] = rb0.y;
        Bs[0][kkA + 2][mmA] = rb0.z; Bs[0][kkA + 3][mmA] = rb0.w;
        Bs[0][kkA + 0][mmA + 32] = rb1.x; Bs[0][kkA + 1][mmA + 32] = rb1.y;
        Bs[0][kkA + 2][mmA + 32] = rb1.z; Bs[0][kkA + 3][mmA + 32] = rb1.w;
    }

    #pragma unroll 1
    for (int it = 0; it < NITER; it++) {
        const int cur = it & 1;
        __syncthreads();
        if (it + 1 < NITER) {
            const int k0 = kbeg + (it + 1) * 16;
            ra0 = *(const float4*)&A[(size_t)(m0 + mmA)      * KS + k0 + kkA];
            ra1 = *(const float4*)&A[(size_t)(m0 + mmA + 32) * KS + k0 + kkA];
            rb0 = *(const float4*)&W[(size_t)(n0 + mmA)      * KS + k0 + kkA];
            rb1 = *(const float4*)&W[(size_t)(n0 + mmA + 32) * KS + k0 + kkA];
        }

        #pragma unroll
        for (int kk = 0; kk < 16; kk++) {
            const float4 a0 = *(const float4*)&As[cur][kk][tm * 8];
            const float4 a1 = *(const float4*)&As[cur][kk][tm * 8 + 4];
            const float4 bb = *(const float4*)&Bs[cur][kk][tn * 4];
            const float a[8] = {a0.x, a0.y, a0.z, a0.w, a1.x, a1.y, a1.z, a1.w};
            const float bv[4] = {bb.x, bb.y, bb.z, bb.w};
            #pragma unroll
            for (int i = 0; i < 8; i++)
                #pragma unroll
                for (int j = 0; j < 4; j++)
                    acc[i][j] += a[i] * bv[j];
        }

        if (it + 1 < NITER) {
            const int nxt = cur ^ 1;
            As[nxt][kkA + 0][mmA] = ra0.x; As[nxt][kkA + 1][mmA] = ra0.y;
            As[nxt][kkA + 2][mmA] = ra0.z; As[nxt][kkA + 3][mmA] = ra0.w;
            As[nxt][kkA + 0][mmA + 32] = ra1.x; As[nxt][kkA + 1][mmA + 32] = ra1.y;
            As[nxt][kkA + 2][mmA + 32] = ra1.z; As[nxt][kkA + 3][mmA + 32] = ra1.w;
            Bs[nxt][kkA + 0][mmA] = rb0.x; Bs[nxt][kkA + 1][mmA] = rb0.y;
            Bs[nxt][kkA + 2][mmA] = rb0.z; Bs[nxt][kkA + 3][mmA] = rb0.w;
            Bs[nxt][kkA + 0][mmA + 32] = rb1.x; Bs[nxt][kkA + 1][mmA + 32] = rb1.y;
            Bs[nxt][kkA + 2][mmA + 32] = rb1.z; Bs[nxt][kkA + 3][mmA + 32] = rb1.w;
        }
    }

    float* __restrict__ P = Pbase + (size_t)z * (BATCH * HID);
    #pragma unroll
    for (int i = 0; i < 8; i++) {
        const int mrow = m0 + tm * 8 + i;
        float4 v = make_float4(acc[i][0], acc[i][1], acc[i][2], acc[i][3]);
        *(float4*)&P[(size_t)mrow * HID + n0 + tn * 4] = v;
    }
}

// ---------------------------------------------------------------------------
// Fused: reduce gemm2 partials + bias + relu + dot(W3) + sigmoid -> out
// ---------------------------------------------------------------------------
__global__ __launch_bounds__(256) void reduce2_out_kernel(
    const float* __restrict__ b2, const float* __restrict__ W3,
    const float* __restrict__ b3, float* __restrict__ out)
{
    __shared__ float red[8];
    const int b = blockIdx.x;
    const int n = threadIdx.x;
    const int idx = b * HID + n;
    float v = b2[n] + g_p2[0][idx] + g_p2[1][idx];
    v = fmaxf(v, 0.f) * W3[n];
    #pragma unroll
    for (int off = 16; off; off >>= 1) v += __shfl_down_sync(0xffffffffu, v, off);
    if ((n & 31) == 0) red[n >> 5] = v;
    __syncthreads();
    if (n == 0) {
        float s = 0.f;
        #pragma unroll
        for (int w = 0; w < 8; w++) s += red[w];
        out[b] = 1.f / (1.f + expf(-(s + b3[0])));
    }
}

// ---------------------------------------------------------------------------
extern "C" void kernel_launch(void* const* d_in, const int* in_sizes, int n_in,
                              void* d_out, int out_size)
{
    const float* x  = (const float*)d_in[0];
    const float* W1 = (const float*)d_in[1];
    const float* b1 = (const float*)d_in[2];
    const float* W2 = (const float*)d_in[3];
    const float* b2 = (const float*)d_in[4];
    const float* W3 = (const float*)d_in[5];
    const float* b3 = (const float*)d_in[6];
    float* out = (float*)d_out;

    float *p_h1, *p_p2;
    cudaGetSymbolAddress((void**)&p_h1, g_h1);
    cudaGetSymbolAddress((void**)&p_p2, g_p2);

    tables_kernel<<<1, 512>>>();
    fold_w1_kernel<<<HID * KF / 256, 256>>>(W1);
    fftmean_kernel<<<BATCH, 256>>>(x);

    dim3 g1(BATCH / 128, HID / 64, NZ1);    // (8, 4, 9) = 288 CTAs
    gemm1_mma_kernel<<<g1, 256>>>();
    reduce1_kernel<<<BATCH * HID / 256, 256>>>(b1);

    dim3 g2(BATCH / 64, HID / 64, 2);       // fp32 layer 2
    gemm_splitk_kernel<HID, 8><<<g2, 128>>>(p_h1, W2, p_p2);

    reduce2_out_kernel<<<BATCH, 256>>>(b2, W3, b3, out);
}

// round 8
// speedup vs baseline: 3.2065x; 1.1054x over previous
#include <cuda_runtime.h>
#include <cuda_bf16.h>
#include <math.h>
#include <stdint.h>

#define BATCH 1024
#define FRAMES 31
#define NFFT 2048
#define N2 1024            // packed complex FFT length
#define KF 1152            // folded K: 1025 padded to 3*384
#define HID 256
#define NZ1 9              // gemm1 z: 3 terms x 3 k-chunks
#define NZ2 3              // gemm2 z: 3 terms
#define ASTR 40            // smem row stride (bf16 elems): 32 + 8 pad

// Scratch (allocation-free rule: __device__ globals)
__device__ __align__(16) __nv_bfloat16 g_a_h[BATCH * KF];
__device__ __align__(16) __nv_bfloat16 g_a_l[BATCH * KF];
__device__ __align__(16) __nv_bfloat16 g_w_h[HID * KF];
__device__ __align__(16) __nv_bfloat16 g_w_l[HID * KF];
__device__ __align__(16) __nv_bfloat16 g_w2h[HID * HID];
__device__ __align__(16) __nv_bfloat16 g_w2l[HID * HID];
__device__ __align__(16) __nv_bfloat16 g_h1h[BATCH * HID];
__device__ __align__(16) __nv_bfloat16 g_h1l[BATCH * HID];
__device__ __align__(16) float2 g_tw[N2];
__device__ __align__(16) float2 g_unt[N2 / 2 + 1];
__device__ __align__(16) float g_p1[NZ1][BATCH * HID];
__device__ __align__(16) float g_p2[NZ2][BATCH * HID];

// ---------------------------------------------------------------------------
// helpers
// ---------------------------------------------------------------------------
__device__ __forceinline__ uint32_t s2u(const void* p) {
    uint32_t a;
    asm("{ .reg .u64 t; cvta.to.shared.u64 t, %1; cvt.u32.u64 %0, t; }"
        : "=r"(a) : "l"(p));
    return a;
}
__device__ __forceinline__ void ldsm4(uint32_t& r0, uint32_t& r1, uint32_t& r2,
                                      uint32_t& r3, uint32_t addr) {
    asm volatile("ldmatrix.sync.aligned.m8n8.x4.shared.b16 {%0,%1,%2,%3}, [%4];"
                 : "=r"(r0), "=r"(r1), "=r"(r2), "=r"(r3) : "r"(addr));
}
__device__ __forceinline__ void mma_bf16(float* d, const uint32_t* a, const uint32_t* b) {
    asm volatile(
        "mma.sync.aligned.m16n8k16.row.col.f32.bf16.bf16.f32 "
        "{%0,%1,%2,%3}, {%4,%5,%6,%7}, {%8,%9}, {%0,%1,%2,%3};"
        : "+f"(d[0]), "+f"(d[1]), "+f"(d[2]), "+f"(d[3])
        : "r"(a[0]), "r"(a[1]), "r"(a[2]), "r"(a[3]), "r"(b[0]), "r"(b[1]));
}
__device__ __forceinline__ void bf_split(float v, __nv_bfloat16& h, __nv_bfloat16& l) {
    h = __float2bfloat16(v);
    l = __float2bfloat16(v - __bfloat162float(h));
}

// ---------------------------------------------------------------------------
// Prep: twiddle+untangle tables, fold+split W1, split W2. One kernel.
// grid = HID*KF/256 = 1152 blocks.
// ---------------------------------------------------------------------------
__global__ __launch_bounds__(256) void prep_kernel(const float* __restrict__ W1,
                                                   const float* __restrict__ W2) {
    const int idx = blockIdx.x * 256 + threadIdx.x;

    if (idx < N2) {
        float sv, cv;
        sincosf(-6.28318530717958647692f * (float)idx * (1.0f / N2), &sv, &cv);
        g_tw[idx] = make_float2(cv, sv);
    }
    if (idx <= N2 / 2) {
        float sv, cv;
        sincosf(3.14159265358979323846f * (float)idx * (1.0f / N2), &sv, &cv);
        g_unt[idx] = make_float2(cv, sv);
    }
    if (idx < HID * HID) {
        __nv_bfloat16 h, l;
        bf_split(W2[idx], h, l);
        g_w2h[idx] = h;
        g_w2l[idx] = l;
    }
    if (idx < HID * KF) {
        const int n = idx / KF;
        const int k = idx - n * KF;
        float v;
        if (k == 0)         v = W1[(size_t)n * NFFT];
        else if (k < 1024)  v = W1[(size_t)n * NFFT + k] + W1[(size_t)n * NFFT + (NFFT - k)];
        else if (k == 1024) v = W1[(size_t)n * NFFT + 1024];
        else                v = 0.f;
        __nv_bfloat16 h, l;
        bf_split(v, h, l);
        g_w_h[idx] = h;
        g_w_l[idx] = l;
    }
}

// ---------------------------------------------------------------------------
// Fused frame-mean + real-packed 1024-pt radix-4 FFT + untangle -> bf16 hi/lo.
// ---------------------------------------------------------------------------
__device__ __forceinline__ unsigned rev4_10(unsigned j) {
    unsigned r = __brev(j) >> 22;
    return ((r & 0x155u) << 1) | ((r >> 1) & 0x155u);
}

__global__ __launch_bounds__(256, 8) void fftmean_kernel(const float* __restrict__ x) {
    __shared__ float2 s[N2];        // 8 KB
    __shared__ float2 tw[N2];       // 8 KB

    const int b   = blockIdx.x;
    const int tid = threadIdx.x;
    const float4* __restrict__ p = (const float4*)x + (size_t)b * (FRAMES * NFFT / 4);

    #pragma unroll
    for (int a = tid; a < N2; a += 256) tw[a] = g_tw[a];

    const float inv = 1.0f / FRAMES;
    #pragma unroll
    for (int h = 0; h < 2; h++) {
        const int f = tid + h * 256;
        float4 acc = make_float4(0.f, 0.f, 0.f, 0.f);
        #pragma unroll
        for (int t = 0; t < FRAMES; t++) {
            float4 v = p[f + t * (NFFT / 4)];
            acc.x += v.x; acc.y += v.y; acc.z += v.z; acc.w += v.w;
        }
        s[rev4_10(2 * f)]     = make_float2(acc.x * inv, acc.y * inv);
        s[rev4_10(2 * f + 1)] = make_float2(acc.z * inv, acc.w * inv);
    }
    __syncthreads();

    #pragma unroll
    for (int st = 0; st < 5; st++) {
        const int q    = 1 << (2 * st);
        const int j    = tid & (q - 1);
        const int blk  = tid >> (2 * st);
        const int base = (blk << (2 * st + 2)) + j;
        const int e    = j << (8 - 2 * st);

        float2 x0 = s[base];
        float2 x1 = s[base + q];
        float2 x2 = s[base + 2 * q];
        float2 x3 = s[base + 3 * q];
        if (e) {
            const float2 w1 = tw[e], w2 = tw[2 * e], w3 = tw[3 * e];
            x1 = make_float2(x1.x * w1.x - x1.y * w1.y, x1.x * w1.y + x1.y * w1.x);
            x2 = make_float2(x2.x * w2.x - x2.y * w2.y, x2.x * w2.y + x2.y * w2.x);
            x3 = make_float2(x3.x * w3.x - x3.y * w3.y, x3.x * w3.y + x3.y * w3.x);
        }
        const float2 ap = make_float2(x0.x + x2.x, x0.y + x2.y);
        const float2 am = make_float2(x0.x - x2.x, x0.y - x2.y);
        const float2 bp = make_float2(x1.x + x3.x, x1.y + x3.y);
        const float2 bm = make_float2(x1.x - x3.x, x1.y - x3.y);
        s[base]         = make_float2(ap.x + bp.x, ap.y + bp.y);
        s[base + q]     = make_float2(am.x + bm.y, am.y - bm.x);
        s[base + 2 * q] = make_float2(ap.x - bp.x, ap.y - bp.y);
        s[base + 3 * q] = make_float2(am.x - bm.y, am.y + bm.x);
        __syncthreads();
    }

    __nv_bfloat16* __restrict__ oh = g_a_h + (size_t)b * KF;
    __nv_bfloat16* __restrict__ ol = g_a_l + (size_t)b * KF;
    #pragma unroll
    for (int k = tid; k <= N2 / 2; k += 256) {
        const float2 zk = s[k];
        const float2 z2 = s[(N2 - k) & (N2 - 1)];
        const float2 u  = g_unt[k];
        const float sumr = zk.x + z2.x;
        const float sumi = zk.y + z2.y;
        const float difr = zk.x - z2.x;
        float v0 = 0.5f * (sumr + u.x * sumi - u.y * difr);
        float v1 = 0.5f * (sumr - u.x * sumi + u.y * difr);
        __nv_bfloat16 h, l;
        bf_split(v0, h, l); oh[k] = h;       ol[k] = l;
        bf_split(v1, h, l); oh[N2 - k] = h;  ol[N2 - k] = l;
    }
    const __nv_bfloat16 z16 = __float2bfloat16(0.f);
    for (int k = N2 + 1 + tid; k < KF; k += 256) { oh[k] = z16; ol[k] = z16; }
}

// ---------------------------------------------------------------------------
// bf16 mma GEMM (hi/lo 3-term), generic over K stride / k-iters / k-splits.
// BM=128, BN=128, BK=32, 256 threads (8 warps, warp tile 64x32).
// grid (M/128, N/128, 3*KSPL); z = term*KSPL + kchunk.
// ---------------------------------------------------------------------------
template <int KS, int KITERS, int KSPL>
__global__ __launch_bounds__(256) void gemm_mma_kernel(
    const __nv_bfloat16* __restrict__ Ah, const __nv_bfloat16* __restrict__ Al,
    const __nv_bfloat16* __restrict__ Wh, const __nv_bfloat16* __restrict__ Wl,
    float* __restrict__ Pbase)
{
    __shared__ __nv_bfloat16 As[2][128 * ASTR];   // 20 KB
    __shared__ __nv_bfloat16 Bs[2][128 * ASTR];   // 20 KB

    const int tid  = threadIdx.x;
    const int wid  = tid >> 5;
    const int lane = tid & 31;
    const int wm0  = (wid & 1) * 64;     // warp m offset
    const int wn0  = (wid >> 1) * 32;    // warp n offset
    const int m0   = blockIdx.x * 128;
    const int n0   = blockIdx.y * 128;
    const int z    = blockIdx.z;
    const int term = z / KSPL;
    const int kbeg = (z - term * KSPL) * (KITERS * 32);

    const __nv_bfloat16* __restrict__ A = (term == 1) ? Al : Ah;
    const __nv_bfloat16* __restrict__ W = (term == 2) ? Wl : Wh;

    // fill coords: 512 16B chunks per array, 2 per thread
    const int fr0 = tid >> 1;                 // c = tid*2 .. +1 -> interleave instead:
    // use c = tid + i*256: row = c>>2, col = (c&3)*8
    // ldmatrix lane addressing
    const int a_row = (lane & 7) + ((lane >> 3) & 1) * 8;
    const int a_col = (lane >> 4) * 8;
    const int b_row = ((lane >> 4) & 1) * 8 + (lane & 7);
    const int b_col = ((lane >> 3) & 1) * 8;
    (void)fr0;

    float acc[4][4][4] = {};
    uint4 rA[2], rB[2];

    // preload tile 0
    #pragma unroll
    for (int i = 0; i < 2; i++) {
        const int c   = tid + i * 256;
        const int row = c >> 2;
        const int cc  = (c & 3) * 8;
        *(uint4*)&As[0][row * ASTR + cc] =
            *(const uint4*)&A[(size_t)(m0 + row) * KS + kbeg + cc];
        *(uint4*)&Bs[0][row * ASTR + cc] =
            *(const uint4*)&W[(size_t)(n0 + row) * KS + kbeg + cc];
    }

    #pragma unroll 1
    for (int it = 0; it < KITERS; it++) {
        const int cur = it & 1;
        __syncthreads();
        if (it + 1 < KITERS) {
            const int k0 = kbeg + (it + 1) * 32;
            #pragma unroll
            for (int i = 0; i < 2; i++) {
                const int c   = tid + i * 256;
                const int row = c >> 2;
                const int cc  = (c & 3) * 8;
                rA[i] = *(const uint4*)&A[(size_t)(m0 + row) * KS + k0 + cc];
                rB[i] = *(const uint4*)&W[(size_t)(n0 + row) * KS + k0 + cc];
            }
        }

        const uint32_t baseA = s2u(&As[cur][0]);
        const uint32_t baseB = s2u(&Bs[cur][0]);
        #pragma unroll
        for (int kk = 0; kk < 2; kk++) {
            uint32_t bfr[4][2];
            #pragma unroll
            for (int np = 0; np < 2; np++) {
                uint32_t r0, r1, r2, r3;
                uint32_t addr = baseB +
                    (uint32_t)(((wn0 + np * 16 + b_row) * ASTR + kk * 16 + b_col) * 2);
                ldsm4(r0, r1, r2, r3, addr);
                bfr[np * 2][0] = r0;     bfr[np * 2][1] = r1;
                bfr[np * 2 + 1][0] = r2; bfr[np * 2 + 1][1] = r3;
            }
            #pragma unroll
            for (int mi = 0; mi < 4; mi++) {
                uint32_t afr[4];
                uint32_t addr = baseA +
                    (uint32_t)(((wm0 + mi * 16 + a_row) * ASTR + kk * 16 + a_col) * 2);
                ldsm4(afr[0], afr[1], afr[2], afr[3], addr);
                #pragma unroll
                for (int ni = 0; ni < 4; ni++)
                    mma_bf16(acc[mi][ni], afr, bfr[ni]);
            }
        }

        if (it + 1 < KITERS) {
            const int nxt = cur ^ 1;
            #pragma unroll
            for (int i = 0; i < 2; i++) {
                const int c   = tid + i * 256;
                const int row = c >> 2;
                const int cc  = (c & 3) * 8;
                *(uint4*)&As[nxt][row * ASTR + cc] = rA[i];
                *(uint4*)&Bs[nxt][row * ASTR + cc] = rB[i];
            }
        }
    }

    float* __restrict__ P = Pbase + (size_t)z * (BATCH * HID);
    const int t4 = lane >> 2;
    const int t2 = (lane & 3) * 2;
    #pragma unroll
    for (int mi = 0; mi < 4; mi++) {
        const int row = m0 + wm0 + mi * 16 + t4;
        #pragma unroll
        for (int ni = 0; ni < 4; ni++) {
            const int col = n0 + wn0 + ni * 8 + t2;
            *(float2*)&P[(size_t)row * HID + col] =
                make_float2(acc[mi][ni][0], acc[mi][ni][1]);
            *(float2*)&P[(size_t)(row + 8) * HID + col] =
                make_float2(acc[mi][ni][2], acc[mi][ni][3]);
        }
    }
}

// ---------------------------------------------------------------------------
// Reduce gemm1 partials + bias + relu -> h1 bf16 hi/lo
// ---------------------------------------------------------------------------
__global__ __launch_bounds__(256) void reduce1_kernel(const float* __restrict__ bias) {
    const int idx = blockIdx.x * 256 + threadIdx.x;
    const int n = idx & (HID - 1);
    float v = bias[n];
    #pragma unroll
    for (int zz = 0; zz < NZ1; zz++) v += g_p1[zz][idx];
    v = fmaxf(v, 0.f);
    __nv_bfloat16 h, l;
    bf_split(v, h, l);
    g_h1h[idx] = h;
    g_h1l[idx] = l;
}

// ---------------------------------------------------------------------------
// Fused: reduce gemm2 partials + bias + relu + dot(W3) + sigmoid -> out
// ---------------------------------------------------------------------------
__global__ __launch_bounds__(256) void reduce2_out_kernel(
    const float* __restrict__ b2, const float* __restrict__ W3,
    const float* __restrict__ b3, float* __restrict__ out)
{
    __shared__ float red[8];
    const int b = blockIdx.x;
    const int n = threadIdx.x;
    const int idx = b * HID + n;
    float v = b2[n] + g_p2[0][idx] + g_p2[1][idx] + g_p2[2][idx];
    v = fmaxf(v, 0.f) * W3[n];
    #pragma unroll
    for (int off = 16; off; off >>= 1) v += __shfl_down_sync(0xffffffffu, v, off);
    if ((n & 31) == 0) red[n >> 5] = v;
    __syncthreads();
    if (n == 0) {
        float s = 0.f;
        #pragma unroll
        for (int w = 0; w < 8; w++) s += red[w];
        out[b] = 1.f / (1.f + expf(-(s + b3[0])));
    }
}

// ---------------------------------------------------------------------------
extern "C" void kernel_launch(void* const* d_in, const int* in_sizes, int n_in,
                              void* d_out, int out_size)
{
    const float* x  = (const float*)d_in[0];
    const float* W1 = (const float*)d_in[1];
    const float* b1 = (const float*)d_in[2];
    const float* W2 = (const float*)d_in[3];
    const float* b2 = (const float*)d_in[4];
    const float* W3 = (const float*)d_in[5];
    const float* b3 = (const float*)d_in[6];
    float* out = (float*)d_out;

    __nv_bfloat16 *p_ah, *p_al, *p_wh, *p_wl, *p_w2h, *p_w2l, *p_h1h, *p_h1l;
    float *p_p1, *p_p2;
    cudaGetSymbolAddress((void**)&p_ah,  g_a_h);
    cudaGetSymbolAddress((void**)&p_al,  g_a_l);
    cudaGetSymbolAddress((void**)&p_wh,  g_w_h);
    cudaGetSymbolAddress((void**)&p_wl,  g_w_l);
    cudaGetSymbolAddress((void**)&p_w2h, g_w2h);
    cudaGetSymbolAddress((void**)&p_w2l, g_w2l);
    cudaGetSymbolAddress((void**)&p_h1h, g_h1h);
    cudaGetSymbolAddress((void**)&p_h1l, g_h1l);
    cudaGetSymbolAddress((void**)&p_p1,  g_p1);
    cudaGetSymbolAddress((void**)&p_p2,  g_p2);

    prep_kernel<<<HID * KF / 256, 256>>>(W1, W2);
    fftmean_kernel<<<BATCH, 256>>>(x);

    // layer 1: K=1152 = 3 chunks x 384 (12 iters), 3 terms -> z = 9
    dim3 g1(BATCH / 128, HID / 128, NZ1);    // (8, 2, 9) = 144 CTAs
    gemm_mma_kernel<KF, 12, 3><<<g1, 256>>>(p_ah, p_al, p_wh, p_wl, p_p1);
    reduce1_kernel<<<BATCH * HID / 256, 256>>>(b1);

    // layer 2: K=256 (8 iters), 3 terms -> z = 3
    dim3 g2(BATCH / 128, HID / 128, NZ2);    // (8, 2, 3) = 48 CTAs
    gemm_mma_kernel<HID, 8, 1><<<g2, 256>>>(p_h1h, p_h1l, p_w2h, p_w2l, p_p2);

    reduce2_out_kernel<<<BATCH, 256>>>(b2, W3, b3, out);
}